// round 5
// baseline (speedup 1.0000x reference)
#include <cuda_runtime.h>
#include <math.h>

// Problem constants
#define BB   16
#define NN   4096
#define CC   384
#define NH   12
#define HD   32
#define WSZ  8
#define NWIN 1024            // B * (8*8) windows
#define MTOT 65536           // B * N rows
#define QKVN 1152            // 3*C

// Scratch (allocation-free: device globals)
static __device__ float g_qkv[(size_t)MTOT * QKVN];  // window-ordered [m][3C]
static __device__ float g_att[(size_t)MTOT * CC];    // window-ordered attention out

// Map window-ordered row m -> original row index (b*4096 + n)
__device__ __forceinline__ int win_to_orig(int m) {
    int b  = m >> 12;          // 4096 rows per batch
    int r  = m & 4095;
    int g  = r >> 6;           // window id 0..63
    int s  = r & 63;           // in-window token 0..63
    int gh = g >> 3, gw = g & 7;
    int sh = s >> 3, sw = s & 7;
    int n  = ((gh << 3) + sh) * 64 + (gw << 3) + sw;
    return (b << 12) + n;
}

// ---------------------------------------------------------------------------
// Tiled fp32 GEMM: C[64x64 tile] = A(65536 x 384) @ B(384 x N)
// MODE 0: gather A rows through window mapping (A = x), write C directly
// MODE 1: read A rows directly, scatter C rows back to original order, + bias
// ---------------------------------------------------------------------------
template<int MODE, int N>
__global__ __launch_bounds__(256) void gemm_k(const float* __restrict__ A,
                                              const float* __restrict__ B,
                                              float* __restrict__ C,
                                              const float* __restrict__ bias)
{
    __shared__ float As[16][65];   // padded: transposed A tile [k][m]
    __shared__ float Bs[16][64];   // [k][n]

    const int n0  = blockIdx.x * 64;
    const int m0  = blockIdx.y * 64;
    const int tid = threadIdx.x;          // 256
    const int tx  = tid & 15;
    const int ty  = tid >> 4;

    // A-tile loader: thread -> (row 0..63, 4 consecutive k)
    const int lr = tid >> 2;
    const int lc = (tid & 3) * 4;
    const int arow = m0 + lr;
    const int asrc = (MODE == 0) ? win_to_orig(arow) : arow;
    const float* aptr = A + (size_t)asrc * CC + lc;

    // B-tile loader: thread -> (k-row 0..15, 4 consecutive n)
    const int br = tid >> 4;
    const int bc = (tid & 15) * 4;
    const float* bptr = B + (size_t)br * N + n0 + bc;

    float acc[4][4] = {};

    for (int k0 = 0; k0 < CC; k0 += 16) {
        float4 av = *(const float4*)(aptr + k0);
        As[lc + 0][lr] = av.x;
        As[lc + 1][lr] = av.y;
        As[lc + 2][lr] = av.z;
        As[lc + 3][lr] = av.w;
        *(float4*)&Bs[br][bc] = *(const float4*)(bptr + (size_t)k0 * N);
        __syncthreads();
        #pragma unroll
        for (int kk = 0; kk < 16; kk++) {
            float a[4], b[4];
            #pragma unroll
            for (int i = 0; i < 4; i++) a[i] = As[kk][ty * 4 + i];
            #pragma unroll
            for (int j = 0; j < 4; j++) b[j] = Bs[kk][tx * 4 + j];
            #pragma unroll
            for (int i = 0; i < 4; i++)
                #pragma unroll
                for (int j = 0; j < 4; j++)
                    acc[i][j] += a[i] * b[j];
        }
        __syncthreads();
    }

    #pragma unroll
    for (int i = 0; i < 4; i++) {
        int m = m0 + ty * 4 + i;
        int crow = (MODE == 1) ? win_to_orig(m) : m;
        float4 v;
        v.x = acc[i][0]; v.y = acc[i][1]; v.z = acc[i][2]; v.w = acc[i][3];
        if (MODE == 1) {
            v.x += bias[n0 + tx * 4 + 0];
            v.y += bias[n0 + tx * 4 + 1];
            v.z += bias[n0 + tx * 4 + 2];
            v.w += bias[n0 + tx * 4 + 3];
        }
        *(float4*)(C + (size_t)crow * N + n0 + tx * 4) = v;
    }
}

// ---------------------------------------------------------------------------
// Attention: one block per (head, window). 64 threads = 64 query rows.
// K,V tiles in smem; q, logits, output accumulator in registers.
// ---------------------------------------------------------------------------
__global__ __launch_bounds__(64) void attn_k()
{
    const int h   = blockIdx.x;     // 0..11
    const int win = blockIdx.y;     // 0..1023
    const int tid = threadIdx.x;    // 0..63

    __shared__ float Ks[64][HD];
    __shared__ float Vs[64][HD];

    const float* base = g_qkv + (size_t)win * 64 * QKVN;
    const int koff = CC + h * HD;       // k columns
    const int voff = 2 * CC + h * HD;   // v columns

    // cooperative K/V load: 64 rows x 8 float4 each
    for (int j = tid; j < 64 * 8; j += 64) {
        int row = j >> 3;
        int c   = (j & 7) * 4;
        const float* rp = base + (size_t)row * QKVN;
        *(float4*)&Ks[row][c] = *(const float4*)(rp + koff + c);
        *(float4*)&Vs[row][c] = *(const float4*)(rp + voff + c);
    }
    __syncthreads();

    // q row in registers
    float q[HD];
    const float* qp = base + (size_t)tid * QKVN + h * HD;
    #pragma unroll
    for (int d = 0; d < HD; d += 4) {
        float4 t = *(const float4*)(qp + d);
        q[d] = t.x; q[d + 1] = t.y; q[d + 2] = t.z; q[d + 3] = t.w;
    }

    const float scale = 0.17677669529663687f;  // 1/sqrt(32)

    float p[64];
    float mx = -1e30f;
    #pragma unroll
    for (int j = 0; j < 64; j++) {
        float s = 0.f;
        #pragma unroll
        for (int d = 0; d < HD; d++) s += q[d] * Ks[j][d];
        s *= scale;
        p[j] = s;
        mx = fmaxf(mx, s);
    }
    float sum = 0.f;
    #pragma unroll
    for (int j = 0; j < 64; j++) {
        p[j] = expf(p[j] - mx);
        sum += p[j];
    }
    const float inv = 1.f / sum;

    float o[HD] = {};
    #pragma unroll
    for (int j = 0; j < 64; j++) {
        float pj = p[j] * inv;
        #pragma unroll
        for (int d = 0; d < HD; d++) o[d] += pj * Vs[j][d];
    }

    float* op = g_att + (size_t)(win * 64 + tid) * CC + h * HD;
    #pragma unroll
    for (int d = 0; d < HD; d += 4) {
        float4 v; v.x = o[d]; v.y = o[d + 1]; v.z = o[d + 2]; v.w = o[d + 3];
        *(float4*)(op + d) = v;
    }
}

// ---------------------------------------------------------------------------
extern "C" void kernel_launch(void* const* d_in, const int* in_sizes, int n_in,
                              void* d_out, int out_size)
{
    const float* x      = (const float*)d_in[0];
    const float* qkv_w  = (const float*)d_in[1];
    const float* proj_w = (const float*)d_in[2];
    const float* proj_b = (const float*)d_in[3];
    float* out = (float*)d_out;

    void* qkv_p = nullptr;
    void* att_p = nullptr;
    cudaGetSymbolAddress(&qkv_p, g_qkv);
    cudaGetSymbolAddress(&att_p, g_att);

    // 1) QKV projection, window-gathered rows: [65536,384] @ [384,1152]
    gemm_k<0, QKVN><<<dim3(QKVN / 64, MTOT / 64), 256>>>(
        x, qkv_w, (float*)qkv_p, nullptr);

    // 2) Per-window, per-head attention
    attn_k<<<dim3(NH, NWIN), 64>>>();

    // 3) Output projection + bias, rows scattered back: [65536,384] @ [384,384]
    gemm_k<1, CC><<<dim3(CC / 64, MTOT / 64), 256>>>(
        (const float*)att_p, proj_w, out, proj_b);
}

// round 8
// speedup vs baseline: 1.3166x; 1.3166x over previous
#include <cuda_runtime.h>
#include <math.h>

// Problem constants
#define BB   16
#define NN   4096
#define CC   384
#define NH   12
#define HD   32
#define WSZ  8
#define NWIN 1024            // B * (8*8) windows
#define MTOT 65536           // B * N rows
#define QKVN 1152            // 3*C

// Scratch (allocation-free: device globals)
static __device__ float g_qkv[(size_t)MTOT * QKVN];  // window-ordered [m][3C]
static __device__ float g_att[(size_t)MTOT * CC];    // window-ordered attention out

// Map window-ordered row m -> original row index (b*4096 + n)
__device__ __forceinline__ int win_to_orig(int m) {
    int b  = m >> 12;          // 4096 rows per batch
    int r  = m & 4095;
    int g  = r >> 6;           // window id 0..63
    int s  = r & 63;           // in-window token 0..63
    int gh = g >> 3, gw = g & 7;
    int sh = s >> 3, sw = s & 7;
    int n  = ((gh << 3) + sh) * 64 + (gw << 3) + sw;
    return (b << 12) + n;
}

// ---------------------------------------------------------------------------
// fp32 GEMM, 128x128 tile, BK=8, 256 threads, 8x8 micro-tile (split 2x[4]
// in both dims for conflict-free LDS.128), double-buffered smem.
// MODE 0: gather A rows through window mapping (A = x), write C directly
// MODE 1: read A rows directly, scatter C rows back to original order, + bias
// ---------------------------------------------------------------------------
template<int MODE, int N>
__global__ __launch_bounds__(256) void gemm128(const float* __restrict__ A,
                                               const float* __restrict__ B,
                                               float* __restrict__ C,
                                               const float* __restrict__ bias)
{
    __shared__ float As[2][8][132];   // transposed A tile [k][m], pad 4
    __shared__ float Bs[2][8][132];   // [k][n], pad 4 (rows stay 16B aligned)

    const int n0  = blockIdx.x * 128;
    const int m0  = blockIdx.y * 128;
    const int tid = threadIdx.x;          // 256
    const int tx  = tid & 15;
    const int ty  = tid >> 4;

    // A loader: thread -> (row 0..127, k-col 0 or 4)
    const int ar = tid >> 1;
    const int ak = (tid & 1) * 4;
    const int am = m0 + ar;
    const int asrc = (MODE == 0) ? win_to_orig(am) : am;
    const float* aptr = A + (size_t)asrc * CC + ak;

    // B loader: thread -> (k-row 0..7, 4 consecutive n of 128)
    const int bk = tid >> 5;
    const int bn = (tid & 31) * 4;
    const float* bptr = B + (size_t)bk * N + n0 + bn;

    float acc[2][2][4][4] = {};   // [im][jn][i][j]

    // prologue: load k-tile 0 into buffer 0
    {
        float4 av = *(const float4*)(aptr);
        float4 bv = *(const float4*)(bptr);
        As[0][ak + 0][ar] = av.x;
        As[0][ak + 1][ar] = av.y;
        As[0][ak + 2][ar] = av.z;
        As[0][ak + 3][ar] = av.w;
        *(float4*)&Bs[0][bk][bn] = bv;
    }
    __syncthreads();

    int cur = 0;
    for (int k0 = 0; k0 < CC; k0 += 8) {
        const bool has_next = (k0 + 8 < CC);
        float4 av, bv;
        if (has_next) {
            av = *(const float4*)(aptr + k0 + 8);
            bv = *(const float4*)(bptr + (size_t)(k0 + 8) * N);
        }

        #pragma unroll
        for (int kk = 0; kk < 8; kk++) {
            float4 a0 = *(const float4*)&As[cur][kk][ty * 4];
            float4 a1 = *(const float4*)&As[cur][kk][64 + ty * 4];
            float4 b0 = *(const float4*)&Bs[cur][kk][tx * 4];
            float4 b1 = *(const float4*)&Bs[cur][kk][64 + tx * 4];
            float a[2][4] = {{a0.x, a0.y, a0.z, a0.w}, {a1.x, a1.y, a1.z, a1.w}};
            float b[2][4] = {{b0.x, b0.y, b0.z, b0.w}, {b1.x, b1.y, b1.z, b1.w}};
            #pragma unroll
            for (int im = 0; im < 2; im++)
                #pragma unroll
                for (int i = 0; i < 4; i++)
                    #pragma unroll
                    for (int jn = 0; jn < 2; jn++)
                        #pragma unroll
                        for (int j = 0; j < 4; j++)
                            acc[im][jn][i][j] += a[im][i] * b[jn][j];
        }

        if (has_next) {
            int nxt = cur ^ 1;
            As[nxt][ak + 0][ar] = av.x;
            As[nxt][ak + 1][ar] = av.y;
            As[nxt][ak + 2][ar] = av.z;
            As[nxt][ak + 3][ar] = av.w;
            *(float4*)&Bs[nxt][bk][bn] = bv;
            __syncthreads();
            cur = nxt;
        }
    }

    #pragma unroll
    for (int im = 0; im < 2; im++) {
        #pragma unroll
        for (int i = 0; i < 4; i++) {
            int m = m0 + im * 64 + ty * 4 + i;
            int crow = (MODE == 1) ? win_to_orig(m) : m;
            float* crp = C + (size_t)crow * N;
            #pragma unroll
            for (int jn = 0; jn < 2; jn++) {
                int col = n0 + jn * 64 + tx * 4;
                float4 v;
                v.x = acc[im][jn][i][0];
                v.y = acc[im][jn][i][1];
                v.z = acc[im][jn][i][2];
                v.w = acc[im][jn][i][3];
                if (MODE == 1) {
                    v.x += bias[col + 0];
                    v.y += bias[col + 1];
                    v.z += bias[col + 2];
                    v.w += bias[col + 3];
                }
                *(float4*)(crp + col) = v;
            }
        }
    }
}

// ---------------------------------------------------------------------------
// Attention: one block per (head, window). 64 threads = 64 query rows.
// ---------------------------------------------------------------------------
__global__ __launch_bounds__(64) void attn_k()
{
    const int h   = blockIdx.x;     // 0..11
    const int win = blockIdx.y;     // 0..1023
    const int tid = threadIdx.x;    // 0..63

    __shared__ float Ks[64][HD];
    __shared__ float Vs[64][HD];

    const float* base = g_qkv + (size_t)win * 64 * QKVN;
    const int koff = CC + h * HD;       // k columns
    const int voff = 2 * CC + h * HD;   // v columns

    for (int j = tid; j < 64 * 8; j += 64) {
        int row = j >> 3;
        int c   = (j & 7) * 4;
        const float* rp = base + (size_t)row * QKVN;
        *(float4*)&Ks[row][c] = *(const float4*)(rp + koff + c);
        *(float4*)&Vs[row][c] = *(const float4*)(rp + voff + c);
    }
    __syncthreads();

    float q[HD];
    const float* qp = base + (size_t)tid * QKVN + h * HD;
    #pragma unroll
    for (int d = 0; d < HD; d += 4) {
        float4 t = *(const float4*)(qp + d);
        q[d] = t.x; q[d + 1] = t.y; q[d + 2] = t.z; q[d + 3] = t.w;
    }

    const float scale = 0.17677669529663687f;  // 1/sqrt(32)

    float p[64];
    float mx = -1e30f;
    #pragma unroll
    for (int j = 0; j < 64; j++) {
        float s = 0.f;
        #pragma unroll
        for (int d = 0; d < HD; d++) s += q[d] * Ks[j][d];
        s *= scale;
        p[j] = s;
        mx = fmaxf(mx, s);
    }
    float sum = 0.f;
    #pragma unroll
    for (int j = 0; j < 64; j++) {
        p[j] = expf(p[j] - mx);
        sum += p[j];
    }
    const float inv = 1.f / sum;

    float o[HD] = {};
    #pragma unroll
    for (int j = 0; j < 64; j++) {
        float pj = p[j] * inv;
        #pragma unroll
        for (int d = 0; d < HD; d++) o[d] += pj * Vs[j][d];
    }

    float* op = g_att + (size_t)(win * 64 + tid) * CC + h * HD;
    #pragma unroll
    for (int d = 0; d < HD; d += 4) {
        float4 v; v.x = o[d]; v.y = o[d + 1]; v.z = o[d + 2]; v.w = o[d + 3];
        *(float4*)(op + d) = v;
    }
}

// ---------------------------------------------------------------------------
extern "C" void kernel_launch(void* const* d_in, const int* in_sizes, int n_in,
                              void* d_out, int out_size)
{
    const float* x      = (const float*)d_in[0];
    const float* qkv_w  = (const float*)d_in[1];
    const float* proj_w = (const float*)d_in[2];
    const float* proj_b = (const float*)d_in[3];
    float* out = (float*)d_out;

    void* qkv_p = nullptr;
    void* att_p = nullptr;
    cudaGetSymbolAddress(&qkv_p, g_qkv);
    cudaGetSymbolAddress(&att_p, g_att);

    // 1) QKV projection, window-gathered rows: [65536,384] @ [384,1152]
    gemm128<0, QKVN><<<dim3(QKVN / 128, MTOT / 128), 256>>>(
        x, qkv_w, (float*)qkv_p, nullptr);

    // 2) Per-window, per-head attention
    attn_k<<<dim3(NH, NWIN), 64>>>();

    // 3) Output projection + bias, rows scattered back: [65536,384] @ [384,384]
    gemm128<1, CC><<<dim3(CC / 128, MTOT / 128), 256>>>(
        (const float*)att_p, proj_w, out, proj_b);
}

// round 14
// speedup vs baseline: 2.0988x; 1.5941x over previous
#include <cuda_runtime.h>
#include <cuda_bf16.h>
#include <math.h>
#include <stdint.h>

// Problem constants
#define BB   16
#define NN   4096
#define CC   384           // K of both GEMMs
#define NH   12
#define HD   32
#define WSZ  8
#define NWIN 1024
#define MTOT 65536
#define QKVN 1152

#define BK   64            // k-chunk (64 bf16 = 128B row = 8 swizzle chunks)
#define NCH  (CC / BK)     // 6 chunks
#define SM_STAGE 65536     // 4 tiles x 16KB (Ahi,Alo,Bhi,Blo), 128 rows x 128B
#define SM_TOTAL (2 * SM_STAGE)

typedef __nv_bfloat16 bf16;

// ---------------- device scratch (allocation-free) ----------------
static __device__ float g_qkv[(size_t)MTOT * QKVN];   // window-ordered qkv (fp32)
static __device__ bf16  g_xhi[(size_t)MTOT * CC];     // window-gathered x, hi part
static __device__ bf16  g_xlo[(size_t)MTOT * CC];
static __device__ bf16  g_ahi[(size_t)MTOT * CC];     // attention out (window-ordered)
static __device__ bf16  g_alo[(size_t)MTOT * CC];
static __device__ bf16  g_wqhi[(size_t)QKVN * CC];    // qkv_w transposed [n][k]
static __device__ bf16  g_wqlo[(size_t)QKVN * CC];
static __device__ bf16  g_wphi[(size_t)CC * CC];      // proj_w transposed [n][k]
static __device__ bf16  g_wplo[(size_t)CC * CC];

// window-ordered row m -> original row index
__device__ __forceinline__ int win_to_orig(int m) {
    int b  = m >> 12;
    int r  = m & 4095;
    int g  = r >> 6;
    int s  = r & 63;
    int gh = g >> 3, gw = g & 7;
    int sh = s >> 3, sw = s & 7;
    int n  = ((gh << 3) + sh) * 64 + (gw << 3) + sw;
    return (b << 12) + n;
}

// ---------------- PTX helpers (family-common only: sm_80-era) ----------------
__device__ __forceinline__ uint32_t smem_u32(const void* p) {
    uint32_t a;
    asm("{ .reg .u64 t; cvta.to.shared.u64 t, %1; cvt.u32.u64 %0, t; }" : "=r"(a) : "l"(p));
    return a;
}
__device__ __forceinline__ void cp_async16(uint32_t s, const void* g) {
    asm volatile("cp.async.cg.shared.global [%0], [%1], 16;" :: "r"(s), "l"(g) : "memory");
}
#define CP_COMMIT() asm volatile("cp.async.commit_group;" ::: "memory")

__device__ __forceinline__ void ldm4(uint32_t* r, uint32_t addr) {
    asm volatile("ldmatrix.sync.aligned.m8n8.x4.shared.b16 {%0,%1,%2,%3}, [%4];"
                 : "=r"(r[0]), "=r"(r[1]), "=r"(r[2]), "=r"(r[3]) : "r"(addr));
}
__device__ __forceinline__ void mma16816(float* d, const uint32_t* a, const uint32_t* b) {
    asm("mma.sync.aligned.m16n8k16.row.col.f32.bf16.bf16.f32 "
        "{%0,%1,%2,%3}, {%4,%5,%6,%7}, {%8,%9}, {%0,%1,%2,%3};"
        : "+f"(d[0]), "+f"(d[1]), "+f"(d[2]), "+f"(d[3])
        : "r"(a[0]), "r"(a[1]), "r"(a[2]), "r"(a[3]), "r"(b[0]), "r"(b[1]));
}

// ---------------- prep: split+transpose weights ----------------
__global__ void prep_w(const float* __restrict__ qkv_w, const float* __restrict__ proj_w)
{
    int idx = blockIdx.x * blockDim.x + threadIdx.x;
    const int NQ = QKVN * CC;
    if (idx < NQ) {
        int n = idx / CC, k = idx - n * CC;
        float v = qkv_w[(size_t)k * QKVN + n];
        bf16 h = __float2bfloat16(v);
        g_wqhi[idx] = h;
        g_wqlo[idx] = __float2bfloat16(v - __bfloat162float(h));
    } else {
        int j = idx - NQ;
        if (j < CC * CC) {
            int n = j / CC, k = j - n * CC;
            float v = proj_w[(size_t)k * CC + n];
            bf16 h = __float2bfloat16(v);
            g_wphi[j] = h;
            g_wplo[j] = __float2bfloat16(v - __bfloat162float(h));
        }
    }
}

// ---------------- prep: window-gather + split x ----------------
__global__ void prep_x(const float* __restrict__ x)
{
    int idx = blockIdx.x * blockDim.x + threadIdx.x;   // over MTOT * (CC/4)
    int m  = idx / (CC / 4);
    int c4 = (idx - m * (CC / 4)) * 4;
    int src = win_to_orig(m);
    float4 v = *(const float4*)(x + (size_t)src * CC + c4);
    float f[4] = {v.x, v.y, v.z, v.w};
    bf16 hb[4], lb[4];
    #pragma unroll
    for (int i = 0; i < 4; i++) {
        hb[i] = __float2bfloat16(f[i]);
        lb[i] = __float2bfloat16(f[i] - __bfloat162float(hb[i]));
    }
    *(uint2*)(g_xhi + (size_t)m * CC + c4) = *(uint2*)hb;
    *(uint2*)(g_xlo + (size_t)m * CC + c4) = *(uint2*)lb;
}

// ---------------- tensor-core split-bf16 GEMM via mma.sync ----------------
// C[m][n] = sum_k A[m][k]*B[n][k]; A/B pre-split bf16 hi/lo; fp32 out.
// 128x128 block tile, 8 warps (2M x 4N), warp tile 64x32, m16n8k16 frags.
// MODE 0: A=g_x*,  B=g_wq*, C=g_qkv (direct, N=1152)
// MODE 1: A=g_a*,  B=g_wp*, C=out (scatter rows + bias, N=384)
template<int MODE, int N>
__global__ __launch_bounds__(256, 1) void gemm_mma(float* __restrict__ C,
                                                   const float* __restrict__ bias)
{
    extern __shared__ char smem[];
    const uint32_t sb = smem_u32(smem);
    const int tid  = threadIdx.x;
    const int lane = tid & 31;
    const int wid  = tid >> 5;
    const int wm   = wid >> 2;       // 0..1  -> m offset wm*64
    const int wn   = wid & 3;        // 0..3  -> n offset wn*32

    const int m0 = blockIdx.x * 128;
    const int n0 = blockIdx.y * 128;

    const bf16* Ahi = (MODE == 0) ? g_xhi : g_ahi;
    const bf16* Alo = (MODE == 0) ? g_xlo : g_alo;
    const bf16* Bhi = (MODE == 0) ? g_wqhi : g_wphi;
    const bf16* Blo = (MODE == 0) ? g_wqlo : g_wplo;

    // ---- loader geometry: each thread cp.asyncs 4x16B per 16KB tile ----
    const int lrow = tid >> 1;                // 0..127
    const int vc0  = (tid & 1) * 4;           // 16B-chunk cols 0..3 / 4..7
    const bf16* gA0 = Ahi + (size_t)(m0 + lrow) * CC;
    const bf16* gA1 = Alo + (size_t)(m0 + lrow) * CC;
    const bf16* gB0 = Bhi + (size_t)(n0 + lrow) * CC;
    const bf16* gB1 = Blo + (size_t)(n0 + lrow) * CC;
    uint32_t sw[4];
    #pragma unroll
    for (int i = 0; i < 4; i++)
        sw[i] = lrow * 128 + (((vc0 + i) ^ (lrow & 7)) << 4);

    #define LOAD_CHUNK(stage, kc0)                                              \
        do {                                                                    \
            const uint32_t _s = sb + (uint32_t)(stage) * SM_STAGE;              \
            _Pragma("unroll")                                                   \
            for (int i = 0; i < 4; i++) {                                       \
                int off = (kc0) + (vc0 + i) * 8;                                \
                cp_async16(_s +         sw[i], gA0 + off);                      \
                cp_async16(_s + 16384 + sw[i], gA1 + off);                      \
                cp_async16(_s + 32768 + sw[i], gB0 + off);                      \
                cp_async16(_s + 49152 + sw[i], gB1 + off);                      \
            }                                                                   \
            CP_COMMIT();                                                        \
        } while (0)

    // ---- ldmatrix lane geometry ----
    const int q  = lane >> 3;        // matrix id 0..3
    const int rr = lane & 7;
    const int ra  = wm * 64 + rr + (q & 1) * 8;   // + mt*16 (A rows)
    const int kca = q >> 1;                        // A: k-half select
    const int rb  = wn * 32 + rr + (q >> 1) * 8;   // + p*16  (B rows, p = nt pair)
    const int kcb = q & 1;                         // B: k-half select
    const int rax = ra & 7;
    const int rbx = rb & 7;

    float acc[4][4][4] = {};    // [mt][nt][frag]

    // prologue: chunks 0,1 -> stages 0,1
    LOAD_CHUNK(0, 0);
    LOAD_CHUNK(1, BK);

    #pragma unroll 1
    for (int c = 0; c < NCH; c++) {
        if (c < NCH - 1) asm volatile("cp.async.wait_group 1;" ::: "memory");
        else             asm volatile("cp.async.wait_group 0;" ::: "memory");
        __syncthreads();

        const uint32_t stg = sb + (uint32_t)(c & 1) * SM_STAGE;
        #pragma unroll
        for (int ks = 0; ks < 4; ks++) {
            uint32_t ah[4][4], al[4][4], bh[2][4], bl[2][4];
            #pragma unroll
            for (int mt = 0; mt < 4; mt++) {
                uint32_t aoff = (uint32_t)(ra + mt * 16) * 128
                              + (uint32_t)((((ks << 1) | kca) ^ rax) << 4);
                ldm4(ah[mt], stg +         aoff);
                ldm4(al[mt], stg + 16384 + aoff);
            }
            #pragma unroll
            for (int p = 0; p < 2; p++) {
                uint32_t boff = (uint32_t)(rb + p * 16) * 128
                              + (uint32_t)((((ks << 1) | kcb) ^ rbx) << 4);
                ldm4(bh[p], stg + 32768 + boff);
                ldm4(bl[p], stg + 49152 + boff);
            }
            #pragma unroll
            for (int mt = 0; mt < 4; mt++)
                #pragma unroll
                for (int nt = 0; nt < 4; nt++) {
                    const uint32_t* Bh = &bh[nt >> 1][(nt & 1) * 2];
                    const uint32_t* Bl = &bl[nt >> 1][(nt & 1) * 2];
                    mma16816(acc[mt][nt], ah[mt], Bh);
                    mma16816(acc[mt][nt], ah[mt], Bl);
                    mma16816(acc[mt][nt], al[mt], Bh);
                }
        }
        __syncthreads();
        if (c + 2 < NCH) LOAD_CHUNK(c & 1, (c + 2) * BK);
    }

    // ---- epilogue: fragment -> global ----
    const int gr = lane >> 2;        // 0..7
    const int tg = lane & 3;         // 0..3
    #pragma unroll
    for (int mt = 0; mt < 4; mt++) {
        int mrow = m0 + wm * 64 + mt * 16 + gr;
        int r0 = (MODE == 1) ? win_to_orig(mrow)     : mrow;
        int r1 = (MODE == 1) ? win_to_orig(mrow + 8) : mrow + 8;
        float* c0 = C + (size_t)r0 * N;
        float* c1 = C + (size_t)r1 * N;
        #pragma unroll
        for (int nt = 0; nt < 4; nt++) {
            int col = n0 + wn * 32 + nt * 8 + tg * 2;
            float b0 = 0.f, b1 = 0.f;
            if (MODE == 1) { b0 = bias[col]; b1 = bias[col + 1]; }
            float2 v0 = make_float2(acc[mt][nt][0] + b0, acc[mt][nt][1] + b1);
            float2 v1 = make_float2(acc[mt][nt][2] + b0, acc[mt][nt][3] + b1);
            *(float2*)(c0 + col) = v0;
            *(float2*)(c1 + col) = v1;
        }
    }
    #undef LOAD_CHUNK
}

// ---------------- attention (fp32, per window/head) ----------------
__global__ __launch_bounds__(64) void attn_k()
{
    const int h   = blockIdx.x;
    const int win = blockIdx.y;
    const int tid = threadIdx.x;

    __shared__ float Ks[64][HD];
    __shared__ float Vs[64][HD];

    const float* base = g_qkv + (size_t)win * 64 * QKVN;
    const int koff = CC + h * HD;
    const int voff = 2 * CC + h * HD;

    for (int j = tid; j < 64 * 8; j += 64) {
        int r = j >> 3;
        int c = (j & 7) * 4;
        const float* rp = base + (size_t)r * QKVN;
        *(float4*)&Ks[r][c] = *(const float4*)(rp + koff + c);
        *(float4*)&Vs[r][c] = *(const float4*)(rp + voff + c);
    }
    __syncthreads();

    const float scale = 0.17677669529663687f;  // 1/sqrt(32)
    float q[HD];
    const float* qp = base + (size_t)tid * QKVN + h * HD;
    #pragma unroll
    for (int d = 0; d < HD; d += 4) {
        float4 t = *(const float4*)(qp + d);
        q[d] = t.x * scale; q[d+1] = t.y * scale; q[d+2] = t.z * scale; q[d+3] = t.w * scale;
    }

    float p[64];
    float mx = -1e30f;
    #pragma unroll
    for (int j = 0; j < 64; j++) {
        float s = 0.f;
        #pragma unroll
        for (int d = 0; d < HD; d++) s += q[d] * Ks[j][d];
        p[j] = s;
        mx = fmaxf(mx, s);
    }
    float sum = 0.f;
    #pragma unroll
    for (int j = 0; j < 64; j++) {
        p[j] = __expf(p[j] - mx);
        sum += p[j];
    }
    const float inv = 1.f / sum;

    float o[HD] = {};
    #pragma unroll
    for (int j = 0; j < 64; j++) {
        float pj = p[j] * inv;
        #pragma unroll
        for (int d = 0; d < HD; d++) o[d] += pj * Vs[j][d];
    }

    // write split bf16 directly (feeds proj GEMM)
    // HD=32 bf16 = 64 bytes = FOUR uint4 per buffer (round-13 bug: wrote 2)
    __align__(16) bf16 hb[HD];
    __align__(16) bf16 lb[HD];
    #pragma unroll
    for (int d = 0; d < HD; d++) {
        bf16 hv = __float2bfloat16(o[d]);
        hb[d] = hv;
        lb[d] = __float2bfloat16(o[d] - __bfloat162float(hv));
    }
    size_t ob = (size_t)(win * 64 + tid) * CC + h * HD;
    #pragma unroll
    for (int d = 0; d < 4; d++) {
        ((uint4*)(g_ahi + ob))[d] = ((uint4*)hb)[d];
        ((uint4*)(g_alo + ob))[d] = ((uint4*)lb)[d];
    }
}

// ---------------------------------------------------------------------------
extern "C" void kernel_launch(void* const* d_in, const int* in_sizes, int n_in,
                              void* d_out, int out_size)
{
    const float* x      = (const float*)d_in[0];
    const float* qkv_w  = (const float*)d_in[1];
    const float* proj_w = (const float*)d_in[2];
    const float* proj_b = (const float*)d_in[3];
    float* out = (float*)d_out;

    // device-symbol scratch address must come from the runtime, NOT the
    // host-side symbol name (round-12 bug).
    void* qkv_p = nullptr;
    cudaGetSymbolAddress(&qkv_p, g_qkv);

    cudaFuncSetAttribute(gemm_mma<0, QKVN>, cudaFuncAttributeMaxDynamicSharedMemorySize, SM_TOTAL);
    cudaFuncSetAttribute(gemm_mma<1, CC>,   cudaFuncAttributeMaxDynamicSharedMemorySize, SM_TOTAL);

    // 1) weight transpose + split (small)
    prep_w<<<(QKVN * CC + CC * CC + 255) / 256, 256>>>(qkv_w, proj_w);

    // 2) window-gather + split x
    prep_x<<<(MTOT * (CC / 4)) / 256, 256>>>(x);

    // 3) QKV projection (mma.sync tensor cores)
    gemm_mma<0, QKVN><<<dim3(MTOT / 128, QKVN / 128), 256, SM_TOTAL>>>((float*)qkv_p, nullptr);

    // 4) attention (writes split-bf16 output)
    attn_k<<<dim3(NH, NWIN), 64>>>();

    // 5) output projection + bias + scatter (mma.sync tensor cores)
    gemm_mma<1, CC><<<dim3(MTOT / 128, CC / 128), 256, SM_TOTAL>>>(out, proj_b);
}

// round 15
// speedup vs baseline: 2.1312x; 1.0154x over previous
#include <cuda_runtime.h>
#include <cuda_bf16.h>
#include <math.h>
#include <stdint.h>

// Problem constants
#define BB   16
#define NN   4096
#define CC   384           // K of both GEMMs
#define NH   12
#define HD   32
#define WSZ  8
#define NWIN 1024
#define MTOT 65536
#define QKVN 1152

#define BK   64            // k-chunk (64 bf16 = 128B row = 8 swizzle chunks)
#define NCH  (CC / BK)     // 6 chunks
#define SM_STAGE 65536     // 4 tiles x 16KB (Ahi,Alo,Bhi,Blo), 128 rows x 128B
#define SM_TOTAL (2 * SM_STAGE)

typedef __nv_bfloat16 bf16;

// ---------------- device scratch (allocation-free) ----------------
static __device__ float g_qkv[(size_t)MTOT * QKVN];   // window-ordered qkv (fp32)
static __device__ bf16  g_xhi[(size_t)MTOT * CC];     // window-gathered x, hi part
static __device__ bf16  g_xlo[(size_t)MTOT * CC];
static __device__ bf16  g_ahi[(size_t)MTOT * CC];     // attention out (window-ordered)
static __device__ bf16  g_alo[(size_t)MTOT * CC];
static __device__ bf16  g_wqhi[(size_t)QKVN * CC];    // qkv_w transposed [n][k]
static __device__ bf16  g_wqlo[(size_t)QKVN * CC];
static __device__ bf16  g_wphi[(size_t)CC * CC];      // proj_w transposed [n][k]
static __device__ bf16  g_wplo[(size_t)CC * CC];

// window-ordered row m -> original row index
__device__ __forceinline__ int win_to_orig(int m) {
    int b  = m >> 12;
    int r  = m & 4095;
    int g  = r >> 6;
    int s  = r & 63;
    int gh = g >> 3, gw = g & 7;
    int sh = s >> 3, sw = s & 7;
    int n  = ((gh << 3) + sh) * 64 + (gw << 3) + sw;
    return (b << 12) + n;
}

// ---------------- PTX helpers (family-common only: sm_80-era) ----------------
__device__ __forceinline__ uint32_t smem_u32(const void* p) {
    uint32_t a;
    asm("{ .reg .u64 t; cvta.to.shared.u64 t, %1; cvt.u32.u64 %0, t; }" : "=r"(a) : "l"(p));
    return a;
}
__device__ __forceinline__ void cp_async16(uint32_t s, const void* g) {
    asm volatile("cp.async.cg.shared.global [%0], [%1], 16;" :: "r"(s), "l"(g) : "memory");
}
#define CP_COMMIT() asm volatile("cp.async.commit_group;" ::: "memory")

__device__ __forceinline__ void ldm4(uint32_t* r, uint32_t addr) {
    asm volatile("ldmatrix.sync.aligned.m8n8.x4.shared.b16 {%0,%1,%2,%3}, [%4];"
                 : "=r"(r[0]), "=r"(r[1]), "=r"(r[2]), "=r"(r[3]) : "r"(addr));
}
__device__ __forceinline__ void mma16816(float* d, const uint32_t* a, const uint32_t* b) {
    asm("mma.sync.aligned.m16n8k16.row.col.f32.bf16.bf16.f32 "
        "{%0,%1,%2,%3}, {%4,%5,%6,%7}, {%8,%9}, {%0,%1,%2,%3};"
        : "+f"(d[0]), "+f"(d[1]), "+f"(d[2]), "+f"(d[3])
        : "r"(a[0]), "r"(a[1]), "r"(a[2]), "r"(a[3]), "r"(b[0]), "r"(b[1]));
}

// ---------------- prep: split+transpose weights ----------------
__global__ void prep_w(const float* __restrict__ qkv_w, const float* __restrict__ proj_w)
{
    int idx = blockIdx.x * blockDim.x + threadIdx.x;
    const int NQ = QKVN * CC;
    if (idx < NQ) {
        int n = idx / CC, k = idx - n * CC;
        float v = qkv_w[(size_t)k * QKVN + n];
        bf16 h = __float2bfloat16(v);
        g_wqhi[idx] = h;
        g_wqlo[idx] = __float2bfloat16(v - __bfloat162float(h));
    } else {
        int j = idx - NQ;
        if (j < CC * CC) {
            int n = j / CC, k = j - n * CC;
            float v = proj_w[(size_t)k * CC + n];
            bf16 h = __float2bfloat16(v);
            g_wphi[j] = h;
            g_wplo[j] = __float2bfloat16(v - __bfloat162float(h));
        }
    }
}

// ---------------- prep: window-gather + split x ----------------
__global__ void prep_x(const float* __restrict__ x)
{
    int idx = blockIdx.x * blockDim.x + threadIdx.x;   // over MTOT * (CC/4)
    int m  = idx / (CC / 4);
    int c4 = (idx - m * (CC / 4)) * 4;
    int src = win_to_orig(m);
    float4 v = *(const float4*)(x + (size_t)src * CC + c4);
    float f[4] = {v.x, v.y, v.z, v.w};
    bf16 hb[4], lb[4];
    #pragma unroll
    for (int i = 0; i < 4; i++) {
        hb[i] = __float2bfloat16(f[i]);
        lb[i] = __float2bfloat16(f[i] - __bfloat162float(hb[i]));
    }
    *(uint2*)(g_xhi + (size_t)m * CC + c4) = *(uint2*)hb;
    *(uint2*)(g_xlo + (size_t)m * CC + c4) = *(uint2*)lb;
}

// ---------------- tensor-core split-bf16 GEMM via mma.sync ----------------
// C[m][n] = sum_k A[m][k]*B[n][k]; A/B pre-split bf16 hi/lo; fp32 out.
// 128x128 block tile, 8 warps (2M x 4N), warp tile 64x32, m16n8k16 frags.
// Grid: x = n-tile (fast-varying) so concurrent blocks share the A tile in L2
// and the (small) B weight matrix stays L2-resident.
// MODE 0: A=g_x*,  B=g_wq*, C=g_qkv (direct, N=1152)
// MODE 1: A=g_a*,  B=g_wp*, C=out (scatter rows + bias, N=384)
template<int MODE, int N>
__global__ __launch_bounds__(256, 1) void gemm_mma(float* __restrict__ C,
                                                   const float* __restrict__ bias)
{
    extern __shared__ char smem[];
    const uint32_t sb = smem_u32(smem);
    const int tid  = threadIdx.x;
    const int lane = tid & 31;
    const int wid  = tid >> 5;
    const int wm   = wid >> 2;       // 0..1  -> m offset wm*64
    const int wn   = wid & 3;        // 0..3  -> n offset wn*32

    const int n0 = blockIdx.x * 128;   // n fast-varying across adjacent blocks
    const int m0 = blockIdx.y * 128;

    const bf16* Ahi = (MODE == 0) ? g_xhi : g_ahi;
    const bf16* Alo = (MODE == 0) ? g_xlo : g_alo;
    const bf16* Bhi = (MODE == 0) ? g_wqhi : g_wphi;
    const bf16* Blo = (MODE == 0) ? g_wqlo : g_wplo;

    // ---- loader geometry: each thread cp.asyncs 4x16B per 16KB tile ----
    const int lrow = tid >> 1;                // 0..127
    const int vc0  = (tid & 1) * 4;           // 16B-chunk cols 0..3 / 4..7
    const bf16* gA0 = Ahi + (size_t)(m0 + lrow) * CC;
    const bf16* gA1 = Alo + (size_t)(m0 + lrow) * CC;
    const bf16* gB0 = Bhi + (size_t)(n0 + lrow) * CC;
    const bf16* gB1 = Blo + (size_t)(n0 + lrow) * CC;
    uint32_t sw[4];
    #pragma unroll
    for (int i = 0; i < 4; i++)
        sw[i] = lrow * 128 + (((vc0 + i) ^ (lrow & 7)) << 4);

    #define LOAD_CHUNK(stage, kc0)                                              \
        do {                                                                    \
            const uint32_t _s = sb + (uint32_t)(stage) * SM_STAGE;              \
            _Pragma("unroll")                                                   \
            for (int i = 0; i < 4; i++) {                                       \
                int off = (kc0) + (vc0 + i) * 8;                                \
                cp_async16(_s +         sw[i], gA0 + off);                      \
                cp_async16(_s + 16384 + sw[i], gA1 + off);                      \
                cp_async16(_s + 32768 + sw[i], gB0 + off);                      \
                cp_async16(_s + 49152 + sw[i], gB1 + off);                      \
            }                                                                   \
            CP_COMMIT();                                                        \
        } while (0)

    // ---- ldmatrix lane geometry ----
    const int q  = lane >> 3;        // matrix id 0..3
    const int rr = lane & 7;
    const int ra  = wm * 64 + rr + (q & 1) * 8;   // + mt*16 (A rows)
    const int kca = q >> 1;                        // A: k-half select
    const int rb  = wn * 32 + rr + (q >> 1) * 8;   // + p*16  (B rows, p = nt pair)
    const int kcb = q & 1;                         // B: k-half select
    const int rax = ra & 7;
    const int rbx = rb & 7;

    float acc[4][4][4] = {};    // [mt][nt][frag]

    // prologue: chunks 0,1 -> stages 0,1
    LOAD_CHUNK(0, 0);
    LOAD_CHUNK(1, BK);

    #pragma unroll 1
    for (int c = 0; c < NCH; c++) {
        if (c < NCH - 1) asm volatile("cp.async.wait_group 1;" ::: "memory");
        else             asm volatile("cp.async.wait_group 0;" ::: "memory");
        __syncthreads();

        const uint32_t stg = sb + (uint32_t)(c & 1) * SM_STAGE;
        #pragma unroll
        for (int ks = 0; ks < 4; ks++) {
            uint32_t ah[4][4], al[4][4], bh[2][4], bl[2][4];
            #pragma unroll
            for (int mt = 0; mt < 4; mt++) {
                uint32_t aoff = (uint32_t)(ra + mt * 16) * 128
                              + (uint32_t)((((ks << 1) | kca) ^ rax) << 4);
                ldm4(ah[mt], stg +         aoff);
                ldm4(al[mt], stg + 16384 + aoff);
            }
            #pragma unroll
            for (int p = 0; p < 2; p++) {
                uint32_t boff = (uint32_t)(rb + p * 16) * 128
                              + (uint32_t)((((ks << 1) | kcb) ^ rbx) << 4);
                ldm4(bh[p], stg + 32768 + boff);
                ldm4(bl[p], stg + 49152 + boff);
            }
            #pragma unroll
            for (int mt = 0; mt < 4; mt++)
                #pragma unroll
                for (int nt = 0; nt < 4; nt++) {
                    const uint32_t* Bh = &bh[nt >> 1][(nt & 1) * 2];
                    const uint32_t* Bl = &bl[nt >> 1][(nt & 1) * 2];
                    mma16816(acc[mt][nt], ah[mt], Bh);
                    mma16816(acc[mt][nt], ah[mt], Bl);
                    mma16816(acc[mt][nt], al[mt], Bh);
                }
        }
        __syncthreads();
        if (c + 2 < NCH) LOAD_CHUNK(c & 1, (c + 2) * BK);
    }

    // ---- epilogue: fragment -> global ----
    const int gr = lane >> 2;        // 0..7
    const int tg = lane & 3;         // 0..3
    #pragma unroll
    for (int mt = 0; mt < 4; mt++) {
        int mrow = m0 + wm * 64 + mt * 16 + gr;
        int r0 = (MODE == 1) ? win_to_orig(mrow)     : mrow;
        int r1 = (MODE == 1) ? win_to_orig(mrow + 8) : mrow + 8;
        float* c0 = C + (size_t)r0 * N;
        float* c1 = C + (size_t)r1 * N;
        #pragma unroll
        for (int nt = 0; nt < 4; nt++) {
            int col = n0 + wn * 32 + nt * 8 + tg * 2;
            float b0 = 0.f, b1 = 0.f;
            if (MODE == 1) { b0 = bias[col]; b1 = bias[col + 1]; }
            float2 v0 = make_float2(acc[mt][nt][0] + b0, acc[mt][nt][1] + b1);
            float2 v1 = make_float2(acc[mt][nt][2] + b0, acc[mt][nt][3] + b1);
            *(float2*)(c0 + col) = v0;
            *(float2*)(c1 + col) = v1;
        }
    }
    #undef LOAD_CHUNK
}

// ---------------- attention (fp32): 2 heads per block, 128 threads ----------
// thread = (head_local = tid>>6, query_row = tid&63). 32KB smem K/V.
__global__ __launch_bounds__(128) void attn_k()
{
    const int hp  = blockIdx.x;     // 0..5 head pair
    const int win = blockIdx.y;     // 0..1023
    const int tid = threadIdx.x;    // 0..127
    const int hl  = tid >> 6;       // 0..1
    const int row = tid & 63;
    const int h   = hp * 2 + hl;

    __shared__ float Ks[2][64][HD];
    __shared__ float Vs[2][64][HD];

    const float* base = g_qkv + (size_t)win * 64 * QKVN;

    // cooperative K/V load for both heads: 2*64*8 float4 pairs / 128 threads
    for (int j = tid; j < 2 * 64 * 8; j += 128) {
        int hh = j >> 9;            // 0..1
        int r  = (j >> 3) & 63;
        int c  = (j & 7) * 4;
        const float* rp = base + (size_t)r * QKVN;
        int koff = CC + (hp * 2 + hh) * HD;
        int voff = 2 * CC + (hp * 2 + hh) * HD;
        *(float4*)&Ks[hh][r][c] = *(const float4*)(rp + koff + c);
        *(float4*)&Vs[hh][r][c] = *(const float4*)(rp + voff + c);
    }
    __syncthreads();

    const float scale = 0.17677669529663687f;  // 1/sqrt(32)
    float q[HD];
    const float* qp = base + (size_t)row * QKVN + h * HD;
    #pragma unroll
    for (int d = 0; d < HD; d += 4) {
        float4 t = *(const float4*)(qp + d);
        q[d] = t.x * scale; q[d+1] = t.y * scale; q[d+2] = t.z * scale; q[d+3] = t.w * scale;
    }

    float p[64];
    float mx = -1e30f;
    #pragma unroll
    for (int j = 0; j < 64; j++) {
        float s = 0.f;
        #pragma unroll
        for (int d = 0; d < HD; d++) s += q[d] * Ks[hl][j][d];
        p[j] = s;
        mx = fmaxf(mx, s);
    }
    float sum = 0.f;
    #pragma unroll
    for (int j = 0; j < 64; j++) {
        p[j] = __expf(p[j] - mx);
        sum += p[j];
    }
    const float inv = 1.f / sum;

    float o[HD] = {};
    #pragma unroll
    for (int j = 0; j < 64; j++) {
        float pj = p[j] * inv;
        #pragma unroll
        for (int d = 0; d < HD; d++) o[d] += pj * Vs[hl][j][d];
    }

    // write split bf16 directly (feeds proj GEMM): HD=32 bf16 = 4 uint4
    __align__(16) bf16 hb[HD];
    __align__(16) bf16 lb[HD];
    #pragma unroll
    for (int d = 0; d < HD; d++) {
        bf16 hv = __float2bfloat16(o[d]);
        hb[d] = hv;
        lb[d] = __float2bfloat16(o[d] - __bfloat162float(hv));
    }
    size_t ob = (size_t)(win * 64 + row) * CC + h * HD;
    #pragma unroll
    for (int d = 0; d < 4; d++) {
        ((uint4*)(g_ahi + ob))[d] = ((uint4*)hb)[d];
        ((uint4*)(g_alo + ob))[d] = ((uint4*)lb)[d];
    }
}

// ---------------------------------------------------------------------------
extern "C" void kernel_launch(void* const* d_in, const int* in_sizes, int n_in,
                              void* d_out, int out_size)
{
    const float* x      = (const float*)d_in[0];
    const float* qkv_w  = (const float*)d_in[1];
    const float* proj_w = (const float*)d_in[2];
    const float* proj_b = (const float*)d_in[3];
    float* out = (float*)d_out;

    // device-symbol scratch address must come from the runtime (round-12 bug).
    void* qkv_p = nullptr;
    cudaGetSymbolAddress(&qkv_p, g_qkv);

    cudaFuncSetAttribute(gemm_mma<0, QKVN>, cudaFuncAttributeMaxDynamicSharedMemorySize, SM_TOTAL);
    cudaFuncSetAttribute(gemm_mma<1, CC>,   cudaFuncAttributeMaxDynamicSharedMemorySize, SM_TOTAL);

    // 1) weight transpose + split (small)
    prep_w<<<(QKVN * CC + CC * CC + 255) / 256, 256>>>(qkv_w, proj_w);

    // 2) window-gather + split x
    prep_x<<<(MTOT * (CC / 4)) / 256, 256>>>(x);

    // 3) QKV projection (mma.sync tensor cores); grid x = n for L2 A-reuse
    gemm_mma<0, QKVN><<<dim3(QKVN / 128, MTOT / 128), 256, SM_TOTAL>>>((float*)qkv_p, nullptr);

    // 4) attention (2 heads/block, writes split-bf16 output)
    attn_k<<<dim3(NH / 2, NWIN), 128>>>();

    // 5) output projection + bias + scatter (mma.sync tensor cores)
    gemm_mma<1, CC><<<dim3(CC / 128, MTOT / 128), 256, SM_TOTAL>>>(out, proj_b);
}

// round 16
// speedup vs baseline: 2.1414x; 1.0048x over previous
#include <cuda_runtime.h>
#include <cuda_bf16.h>
#include <math.h>
#include <stdint.h>

// Problem constants
#define BB   16
#define NN   4096
#define CC   384           // K of both GEMMs
#define NH   12
#define HD   32
#define WSZ  8
#define NWIN 1024
#define MTOT 65536
#define QKVN 1152

#define BK   64            // k-chunk (64 bf16 = 128B row = 8 swizzle chunks)
#define NCH  (CC / BK)     // 6 chunks
#define SM_STAGE 65536     // 4 tiles x 16KB (Ahi,Alo,Bhi,Blo), 128 rows x 128B
#define SM_TOTAL (2 * SM_STAGE)

typedef __nv_bfloat16 bf16;

// ---------------- device scratch (allocation-free) ----------------
static __device__ float g_qkv[(size_t)MTOT * QKVN];   // window-ordered qkv (fp32)
static __device__ bf16  g_xhi[(size_t)MTOT * CC];     // window-gathered x, hi part
static __device__ bf16  g_xlo[(size_t)MTOT * CC];
static __device__ bf16  g_ahi[(size_t)MTOT * CC];     // attention out (window-ordered)
static __device__ bf16  g_alo[(size_t)MTOT * CC];
static __device__ bf16  g_wqhi[(size_t)QKVN * CC];    // qkv_w transposed [n][k]
static __device__ bf16  g_wqlo[(size_t)QKVN * CC];
static __device__ bf16  g_wphi[(size_t)CC * CC];      // proj_w transposed [n][k]
static __device__ bf16  g_wplo[(size_t)CC * CC];

// window-ordered row m -> original row index
__device__ __forceinline__ int win_to_orig(int m) {
    int b  = m >> 12;
    int r  = m & 4095;
    int g  = r >> 6;
    int s  = r & 63;
    int gh = g >> 3, gw = g & 7;
    int sh = s >> 3, sw = s & 7;
    int n  = ((gh << 3) + sh) * 64 + (gw << 3) + sw;
    return (b << 12) + n;
}

// ---------------- PTX helpers (family-common only: sm_80-era) ----------------
__device__ __forceinline__ uint32_t smem_u32(const void* p) {
    uint32_t a;
    asm("{ .reg .u64 t; cvta.to.shared.u64 t, %1; cvt.u32.u64 %0, t; }" : "=r"(a) : "l"(p));
    return a;
}
__device__ __forceinline__ void cp_async16(uint32_t s, const void* g) {
    asm volatile("cp.async.cg.shared.global [%0], [%1], 16;" :: "r"(s), "l"(g) : "memory");
}
#define CP_COMMIT() asm volatile("cp.async.commit_group;" ::: "memory")

__device__ __forceinline__ void ldm4(uint32_t* r, uint32_t addr) {
    asm volatile("ldmatrix.sync.aligned.m8n8.x4.shared.b16 {%0,%1,%2,%3}, [%4];"
                 : "=r"(r[0]), "=r"(r[1]), "=r"(r[2]), "=r"(r[3]) : "r"(addr));
}
__device__ __forceinline__ void mma16816(float* d, const uint32_t* a, const uint32_t* b) {
    asm("mma.sync.aligned.m16n8k16.row.col.f32.bf16.bf16.f32 "
        "{%0,%1,%2,%3}, {%4,%5,%6,%7}, {%8,%9}, {%0,%1,%2,%3};"
        : "+f"(d[0]), "+f"(d[1]), "+f"(d[2]), "+f"(d[3])
        : "r"(a[0]), "r"(a[1]), "r"(a[2]), "r"(a[3]), "r"(b[0]), "r"(b[1]));
}

// ---------------- prep: split+transpose weights ----------------
__global__ void prep_w(const float* __restrict__ qkv_w, const float* __restrict__ proj_w)
{
    int idx = blockIdx.x * blockDim.x + threadIdx.x;
    const int NQ = QKVN * CC;
    if (idx < NQ) {
        int n = idx / CC, k = idx - n * CC;
        float v = qkv_w[(size_t)k * QKVN + n];
        bf16 h = __float2bfloat16(v);
        g_wqhi[idx] = h;
        g_wqlo[idx] = __float2bfloat16(v - __bfloat162float(h));
    } else {
        int j = idx - NQ;
        if (j < CC * CC) {
            int n = j / CC, k = j - n * CC;
            float v = proj_w[(size_t)k * CC + n];
            bf16 h = __float2bfloat16(v);
            g_wphi[j] = h;
            g_wplo[j] = __float2bfloat16(v - __bfloat162float(h));
        }
    }
}

// ---------------- prep: window-gather + split x ----------------
__global__ void prep_x(const float* __restrict__ x)
{
    int idx = blockIdx.x * blockDim.x + threadIdx.x;   // over MTOT * (CC/4)
    int m  = idx / (CC / 4);
    int c4 = (idx - m * (CC / 4)) * 4;
    int src = win_to_orig(m);
    float4 v = *(const float4*)(x + (size_t)src * CC + c4);
    float f[4] = {v.x, v.y, v.z, v.w};
    bf16 hb[4], lb[4];
    #pragma unroll
    for (int i = 0; i < 4; i++) {
        hb[i] = __float2bfloat16(f[i]);
        lb[i] = __float2bfloat16(f[i] - __bfloat162float(hb[i]));
    }
    *(uint2*)(g_xhi + (size_t)m * CC + c4) = *(uint2*)hb;
    *(uint2*)(g_xlo + (size_t)m * CC + c4) = *(uint2*)lb;
}

// ---------------- tensor-core split-bf16 GEMM via mma.sync ----------------
// (unchanged from round 15: 128x128 tile, 8 warps, split-bf16 3-term)
template<int MODE, int N>
__global__ __launch_bounds__(256, 1) void gemm_mma(float* __restrict__ C,
                                                   const float* __restrict__ bias)
{
    extern __shared__ char smem[];
    const uint32_t sb = smem_u32(smem);
    const int tid  = threadIdx.x;
    const int lane = tid & 31;
    const int wid  = tid >> 5;
    const int wm   = wid >> 2;
    const int wn   = wid & 3;

    const int n0 = blockIdx.x * 128;
    const int m0 = blockIdx.y * 128;

    const bf16* Ahi = (MODE == 0) ? g_xhi : g_ahi;
    const bf16* Alo = (MODE == 0) ? g_xlo : g_alo;
    const bf16* Bhi = (MODE == 0) ? g_wqhi : g_wphi;
    const bf16* Blo = (MODE == 0) ? g_wqlo : g_wplo;

    const int lrow = tid >> 1;
    const int vc0  = (tid & 1) * 4;
    const bf16* gA0 = Ahi + (size_t)(m0 + lrow) * CC;
    const bf16* gA1 = Alo + (size_t)(m0 + lrow) * CC;
    const bf16* gB0 = Bhi + (size_t)(n0 + lrow) * CC;
    const bf16* gB1 = Blo + (size_t)(n0 + lrow) * CC;
    uint32_t sw[4];
    #pragma unroll
    for (int i = 0; i < 4; i++)
        sw[i] = lrow * 128 + (((vc0 + i) ^ (lrow & 7)) << 4);

    #define LOAD_CHUNK(stage, kc0)                                              \
        do {                                                                    \
            const uint32_t _s = sb + (uint32_t)(stage) * SM_STAGE;              \
            _Pragma("unroll")                                                   \
            for (int i = 0; i < 4; i++) {                                       \
                int off = (kc0) + (vc0 + i) * 8;                                \
                cp_async16(_s +         sw[i], gA0 + off);                      \
                cp_async16(_s + 16384 + sw[i], gA1 + off);                      \
                cp_async16(_s + 32768 + sw[i], gB0 + off);                      \
                cp_async16(_s + 49152 + sw[i], gB1 + off);                      \
            }                                                                   \
            CP_COMMIT();                                                        \
        } while (0)

    const int q  = lane >> 3;
    const int rr = lane & 7;
    const int ra  = wm * 64 + rr + (q & 1) * 8;
    const int kca = q >> 1;
    const int rb  = wn * 32 + rr + (q >> 1) * 8;
    const int kcb = q & 1;
    const int rax = ra & 7;
    const int rbx = rb & 7;

    float acc[4][4][4] = {};

    LOAD_CHUNK(0, 0);
    LOAD_CHUNK(1, BK);

    #pragma unroll 1
    for (int c = 0; c < NCH; c++) {
        if (c < NCH - 1) asm volatile("cp.async.wait_group 1;" ::: "memory");
        else             asm volatile("cp.async.wait_group 0;" ::: "memory");
        __syncthreads();

        const uint32_t stg = sb + (uint32_t)(c & 1) * SM_STAGE;
        #pragma unroll
        for (int ks = 0; ks < 4; ks++) {
            uint32_t ah[4][4], al[4][4], bh[2][4], bl[2][4];
            #pragma unroll
            for (int mt = 0; mt < 4; mt++) {
                uint32_t aoff = (uint32_t)(ra + mt * 16) * 128
                              + (uint32_t)((((ks << 1) | kca) ^ rax) << 4);
                ldm4(ah[mt], stg +         aoff);
                ldm4(al[mt], stg + 16384 + aoff);
            }
            #pragma unroll
            for (int p = 0; p < 2; p++) {
                uint32_t boff = (uint32_t)(rb + p * 16) * 128
                              + (uint32_t)((((ks << 1) | kcb) ^ rbx) << 4);
                ldm4(bh[p], stg + 32768 + boff);
                ldm4(bl[p], stg + 49152 + boff);
            }
            #pragma unroll
            for (int mt = 0; mt < 4; mt++)
                #pragma unroll
                for (int nt = 0; nt < 4; nt++) {
                    const uint32_t* Bh = &bh[nt >> 1][(nt & 1) * 2];
                    const uint32_t* Bl = &bl[nt >> 1][(nt & 1) * 2];
                    mma16816(acc[mt][nt], ah[mt], Bh);
                    mma16816(acc[mt][nt], ah[mt], Bl);
                    mma16816(acc[mt][nt], al[mt], Bh);
                }
        }
        __syncthreads();
        if (c + 2 < NCH) LOAD_CHUNK(c & 1, (c + 2) * BK);
    }

    const int gr = lane >> 2;
    const int tg = lane & 3;
    #pragma unroll
    for (int mt = 0; mt < 4; mt++) {
        int mrow = m0 + wm * 64 + mt * 16 + gr;
        int r0 = (MODE == 1) ? win_to_orig(mrow)     : mrow;
        int r1 = (MODE == 1) ? win_to_orig(mrow + 8) : mrow + 8;
        float* c0 = C + (size_t)r0 * N;
        float* c1 = C + (size_t)r1 * N;
        #pragma unroll
        for (int nt = 0; nt < 4; nt++) {
            int col = n0 + wn * 32 + nt * 8 + tg * 2;
            float b0 = 0.f, b1 = 0.f;
            if (MODE == 1) { b0 = bias[col]; b1 = bias[col + 1]; }
            float2 v0 = make_float2(acc[mt][nt][0] + b0, acc[mt][nt][1] + b1);
            float2 v1 = make_float2(acc[mt][nt][2] + b0, acc[mt][nt][3] + b1);
            *(float2*)(c0 + col) = v0;
            *(float2*)(c1 + col) = v1;
        }
    }
    #undef LOAD_CHUNK
}

// ---------------- attention: chunked ONLINE softmax (low-register) ----------
// 2 heads/block, 128 threads; thread = (head_local, query_row).
// Register budget: q[32]+o[32]+pl[8]+state ~= 100 regs (was 168 with p[64]).
#define JCH 8
__global__ __launch_bounds__(128) void attn_k()
{
    const int hp  = blockIdx.x;     // 0..5 head pair
    const int win = blockIdx.y;     // 0..1023
    const int tid = threadIdx.x;    // 0..127
    const int hl  = tid >> 6;       // 0..1
    const int row = tid & 63;
    const int h   = hp * 2 + hl;

    __shared__ float Ks[2][64][HD];
    __shared__ float Vs[2][64][HD];

    const float* base = g_qkv + (size_t)win * 64 * QKVN;

    for (int j = tid; j < 2 * 64 * 8; j += 128) {
        int hh = j >> 9;
        int r  = (j >> 3) & 63;
        int c  = (j & 7) * 4;
        const float* rp = base + (size_t)r * QKVN;
        int koff = CC + (hp * 2 + hh) * HD;
        int voff = 2 * CC + (hp * 2 + hh) * HD;
        *(float4*)&Ks[hh][r][c] = *(const float4*)(rp + koff + c);
        *(float4*)&Vs[hh][r][c] = *(const float4*)(rp + voff + c);
    }
    __syncthreads();

    const float scale = 0.17677669529663687f;  // 1/sqrt(32)
    float q[HD];
    const float* qp = base + (size_t)row * QKVN + h * HD;
    #pragma unroll
    for (int d = 0; d < HD; d += 4) {
        float4 t = *(const float4*)(qp + d);
        q[d] = t.x * scale; q[d+1] = t.y * scale; q[d+2] = t.z * scale; q[d+3] = t.w * scale;
    }

    float o[HD] = {};
    float m = -1e30f;
    float s = 0.f;

    #pragma unroll
    for (int jc = 0; jc < 64; jc += JCH) {
        float pl[JCH];
        float cm = -1e30f;
        #pragma unroll
        for (int jj = 0; jj < JCH; jj++) {
            float v = 0.f;
            #pragma unroll
            for (int d = 0; d < HD; d++) v += q[d] * Ks[hl][jc + jj][d];
            pl[jj] = v;
            cm = fmaxf(cm, v);
        }
        float mn   = fmaxf(m, cm);
        float corr = __expf(m - mn);
        s *= corr;
        #pragma unroll
        for (int d = 0; d < HD; d++) o[d] *= corr;
        #pragma unroll
        for (int jj = 0; jj < JCH; jj++) {
            float e = __expf(pl[jj] - mn);
            s += e;
            #pragma unroll
            for (int d = 0; d < HD; d++) o[d] += e * Vs[hl][jc + jj][d];
        }
        m = mn;
    }

    const float inv = 1.f / s;
    #pragma unroll
    for (int d = 0; d < HD; d++) o[d] *= inv;

    // write split bf16 directly (feeds proj GEMM): HD=32 bf16 = 4 uint4
    __align__(16) bf16 hb[HD];
    __align__(16) bf16 lb[HD];
    #pragma unroll
    for (int d = 0; d < HD; d++) {
        bf16 hv = __float2bfloat16(o[d]);
        hb[d] = hv;
        lb[d] = __float2bfloat16(o[d] - __bfloat162float(hv));
    }
    size_t ob = (size_t)(win * 64 + row) * CC + h * HD;
    #pragma unroll
    for (int d = 0; d < 4; d++) {
        ((uint4*)(g_ahi + ob))[d] = ((uint4*)hb)[d];
        ((uint4*)(g_alo + ob))[d] = ((uint4*)lb)[d];
    }
}

// ---------------------------------------------------------------------------
extern "C" void kernel_launch(void* const* d_in, const int* in_sizes, int n_in,
                              void* d_out, int out_size)
{
    const float* x      = (const float*)d_in[0];
    const float* qkv_w  = (const float*)d_in[1];
    const float* proj_w = (const float*)d_in[2];
    const float* proj_b = (const float*)d_in[3];
    float* out = (float*)d_out;

    // device-symbol scratch address must come from the runtime (round-12 bug).
    void* qkv_p = nullptr;
    cudaGetSymbolAddress(&qkv_p, g_qkv);

    cudaFuncSetAttribute(gemm_mma<0, QKVN>, cudaFuncAttributeMaxDynamicSharedMemorySize, SM_TOTAL);
    cudaFuncSetAttribute(gemm_mma<1, CC>,   cudaFuncAttributeMaxDynamicSharedMemorySize, SM_TOTAL);

    // 1) weight transpose + split (small)
    prep_w<<<(QKVN * CC + CC * CC + 255) / 256, 256>>>(qkv_w, proj_w);

    // 2) window-gather + split x
    prep_x<<<(MTOT * (CC / 4)) / 256, 256>>>(x);

    // 3) QKV projection (mma.sync tensor cores)
    gemm_mma<0, QKVN><<<dim3(QKVN / 128, MTOT / 128), 256, SM_TOTAL>>>((float*)qkv_p, nullptr);

    // 4) attention (online softmax, low-register)
    attn_k<<<dim3(NH / 2, NWIN), 128>>>();

    // 5) output projection + bias + scatter (mma.sync tensor cores)
    gemm_mma<1, CC><<<dim3(CC / 128, MTOT / 128), 256, SM_TOTAL>>>(out, proj_b);
}

// round 17
// speedup vs baseline: 2.2318x; 1.0422x over previous
#include <cuda_runtime.h>
#include <cuda_bf16.h>
#include <math.h>
#include <stdint.h>

// Problem constants
#define BB   16
#define NN   4096
#define CC   384           // K of both GEMMs
#define NH   12
#define HD   32
#define WSZ  8
#define NWIN 1024
#define MTOT 65536
#define QKVN 1152

#define BK   64            // k-chunk (64 bf16 = 128B row = 8 swizzle chunks)
#define NCH  (CC / BK)     // 6 chunks
#define SM_STAGE 65536     // 4 tiles x 16KB (Ahi,Alo,Bhi,Blo), 128 rows x 128B
#define SM_TOTAL (2 * SM_STAGE)

#define AT_SMEM (4 * 64 * HD * 2 * 4)   // 4 heads x (K+V) x 64x32 fp32 = 64KB

typedef __nv_bfloat16 bf16;

// ---------------- device scratch (allocation-free) ----------------
static __device__ float g_qkv[(size_t)MTOT * QKVN];   // window-ordered qkv (fp32)
static __device__ bf16  g_xhi[(size_t)MTOT * CC];     // window-gathered x, hi part
static __device__ bf16  g_xlo[(size_t)MTOT * CC];
static __device__ bf16  g_ahi[(size_t)MTOT * CC];     // attention out (window-ordered)
static __device__ bf16  g_alo[(size_t)MTOT * CC];
static __device__ bf16  g_wqhi[(size_t)QKVN * CC];    // qkv_w transposed [n][k]
static __device__ bf16  g_wqlo[(size_t)QKVN * CC];
static __device__ bf16  g_wphi[(size_t)CC * CC];      // proj_w transposed [n][k]
static __device__ bf16  g_wplo[(size_t)CC * CC];

// window-ordered row m -> original row index
__device__ __forceinline__ int win_to_orig(int m) {
    int b  = m >> 12;
    int r  = m & 4095;
    int g  = r >> 6;
    int s  = r & 63;
    int gh = g >> 3, gw = g & 7;
    int sh = s >> 3, sw = s & 7;
    int n  = ((gh << 3) + sh) * 64 + (gw << 3) + sw;
    return (b << 12) + n;
}

// ---------------- PTX helpers (family-common only: sm_80-era) ----------------
__device__ __forceinline__ uint32_t smem_u32(const void* p) {
    uint32_t a;
    asm("{ .reg .u64 t; cvta.to.shared.u64 t, %1; cvt.u32.u64 %0, t; }" : "=r"(a) : "l"(p));
    return a;
}
__device__ __forceinline__ void cp_async16(uint32_t s, const void* g) {
    asm volatile("cp.async.cg.shared.global [%0], [%1], 16;" :: "r"(s), "l"(g) : "memory");
}
#define CP_COMMIT() asm volatile("cp.async.commit_group;" ::: "memory")

__device__ __forceinline__ void ldm4(uint32_t* r, uint32_t addr) {
    asm volatile("ldmatrix.sync.aligned.m8n8.x4.shared.b16 {%0,%1,%2,%3}, [%4];"
                 : "=r"(r[0]), "=r"(r[1]), "=r"(r[2]), "=r"(r[3]) : "r"(addr));
}
__device__ __forceinline__ void mma16816(float* d, const uint32_t* a, const uint32_t* b) {
    asm("mma.sync.aligned.m16n8k16.row.col.f32.bf16.bf16.f32 "
        "{%0,%1,%2,%3}, {%4,%5,%6,%7}, {%8,%9}, {%0,%1,%2,%3};"
        : "+f"(d[0]), "+f"(d[1]), "+f"(d[2]), "+f"(d[3])
        : "r"(a[0]), "r"(a[1]), "r"(a[2]), "r"(a[3]), "r"(b[0]), "r"(b[1]));
}

// ---------------- prep: split+transpose weights ----------------
__global__ void prep_w(const float* __restrict__ qkv_w, const float* __restrict__ proj_w)
{
    int idx = blockIdx.x * blockDim.x + threadIdx.x;
    const int NQ = QKVN * CC;
    if (idx < NQ) {
        int n = idx / CC, k = idx - n * CC;
        float v = qkv_w[(size_t)k * QKVN + n];
        bf16 h = __float2bfloat16(v);
        g_wqhi[idx] = h;
        g_wqlo[idx] = __float2bfloat16(v - __bfloat162float(h));
    } else {
        int j = idx - NQ;
        if (j < CC * CC) {
            int n = j / CC, k = j - n * CC;
            float v = proj_w[(size_t)k * CC + n];
            bf16 h = __float2bfloat16(v);
            g_wphi[j] = h;
            g_wplo[j] = __float2bfloat16(v - __bfloat162float(h));
        }
    }
}

// ---------------- prep: window-gather + split x ----------------
__global__ void prep_x(const float* __restrict__ x)
{
    int idx = blockIdx.x * blockDim.x + threadIdx.x;   // over MTOT * (CC/4)
    int m  = idx / (CC / 4);
    int c4 = (idx - m * (CC / 4)) * 4;
    int src = win_to_orig(m);
    float4 v = *(const float4*)(x + (size_t)src * CC + c4);
    float f[4] = {v.x, v.y, v.z, v.w};
    bf16 hb[4], lb[4];
    #pragma unroll
    for (int i = 0; i < 4; i++) {
        hb[i] = __float2bfloat16(f[i]);
        lb[i] = __float2bfloat16(f[i] - __bfloat162float(hb[i]));
    }
    *(uint2*)(g_xhi + (size_t)m * CC + c4) = *(uint2*)hb;
    *(uint2*)(g_xlo + (size_t)m * CC + c4) = *(uint2*)lb;
}

// ---------------- tensor-core split-bf16 GEMM via mma.sync ----------------
// (unchanged: 128x128 tile, 8 warps, split-bf16 3-term)
template<int MODE, int N>
__global__ __launch_bounds__(256, 1) void gemm_mma(float* __restrict__ C,
                                                   const float* __restrict__ bias)
{
    extern __shared__ char smem[];
    const uint32_t sb = smem_u32(smem);
    const int tid  = threadIdx.x;
    const int lane = tid & 31;
    const int wid  = tid >> 5;
    const int wm   = wid >> 2;
    const int wn   = wid & 3;

    const int n0 = blockIdx.x * 128;
    const int m0 = blockIdx.y * 128;

    const bf16* Ahi = (MODE == 0) ? g_xhi : g_ahi;
    const bf16* Alo = (MODE == 0) ? g_xlo : g_alo;
    const bf16* Bhi = (MODE == 0) ? g_wqhi : g_wphi;
    const bf16* Blo = (MODE == 0) ? g_wqlo : g_wplo;

    const int lrow = tid >> 1;
    const int vc0  = (tid & 1) * 4;
    const bf16* gA0 = Ahi + (size_t)(m0 + lrow) * CC;
    const bf16* gA1 = Alo + (size_t)(m0 + lrow) * CC;
    const bf16* gB0 = Bhi + (size_t)(n0 + lrow) * CC;
    const bf16* gB1 = Blo + (size_t)(n0 + lrow) * CC;
    uint32_t sw[4];
    #pragma unroll
    for (int i = 0; i < 4; i++)
        sw[i] = lrow * 128 + (((vc0 + i) ^ (lrow & 7)) << 4);

    #define LOAD_CHUNK(stage, kc0)                                              \
        do {                                                                    \
            const uint32_t _s = sb + (uint32_t)(stage) * SM_STAGE;              \
            _Pragma("unroll")                                                   \
            for (int i = 0; i < 4; i++) {                                       \
                int off = (kc0) + (vc0 + i) * 8;                                \
                cp_async16(_s +         sw[i], gA0 + off);                      \
                cp_async16(_s + 16384 + sw[i], gA1 + off);                      \
                cp_async16(_s + 32768 + sw[i], gB0 + off);                      \
                cp_async16(_s + 49152 + sw[i], gB1 + off);                      \
            }                                                                   \
            CP_COMMIT();                                                        \
        } while (0)

    const int q  = lane >> 3;
    const int rr = lane & 7;
    const int ra  = wm * 64 + rr + (q & 1) * 8;
    const int kca = q >> 1;
    const int rb  = wn * 32 + rr + (q >> 1) * 8;
    const int kcb = q & 1;
    const int rax = ra & 7;
    const int rbx = rb & 7;

    float acc[4][4][4] = {};

    LOAD_CHUNK(0, 0);
    LOAD_CHUNK(1, BK);

    #pragma unroll 1
    for (int c = 0; c < NCH; c++) {
        if (c < NCH - 1) asm volatile("cp.async.wait_group 1;" ::: "memory");
        else             asm volatile("cp.async.wait_group 0;" ::: "memory");
        __syncthreads();

        const uint32_t stg = sb + (uint32_t)(c & 1) * SM_STAGE;
        #pragma unroll
        for (int ks = 0; ks < 4; ks++) {
            uint32_t ah[4][4], al[4][4], bh[2][4], bl[2][4];
            #pragma unroll
            for (int mt = 0; mt < 4; mt++) {
                uint32_t aoff = (uint32_t)(ra + mt * 16) * 128
                              + (uint32_t)((((ks << 1) | kca) ^ rax) << 4);
                ldm4(ah[mt], stg +         aoff);
                ldm4(al[mt], stg + 16384 + aoff);
            }
            #pragma unroll
            for (int p = 0; p < 2; p++) {
                uint32_t boff = (uint32_t)(rb + p * 16) * 128
                              + (uint32_t)((((ks << 1) | kcb) ^ rbx) << 4);
                ldm4(bh[p], stg + 32768 + boff);
                ldm4(bl[p], stg + 49152 + boff);
            }
            #pragma unroll
            for (int mt = 0; mt < 4; mt++)
                #pragma unroll
                for (int nt = 0; nt < 4; nt++) {
                    const uint32_t* Bh = &bh[nt >> 1][(nt & 1) * 2];
                    const uint32_t* Bl = &bl[nt >> 1][(nt & 1) * 2];
                    mma16816(acc[mt][nt], ah[mt], Bh);
                    mma16816(acc[mt][nt], ah[mt], Bl);
                    mma16816(acc[mt][nt], al[mt], Bh);
                }
        }
        __syncthreads();
        if (c + 2 < NCH) LOAD_CHUNK(c & 1, (c + 2) * BK);
    }

    const int gr = lane >> 2;
    const int tg = lane & 3;
    #pragma unroll
    for (int mt = 0; mt < 4; mt++) {
        int mrow = m0 + wm * 64 + mt * 16 + gr;
        int r0 = (MODE == 1) ? win_to_orig(mrow)     : mrow;
        int r1 = (MODE == 1) ? win_to_orig(mrow + 8) : mrow + 8;
        float* c0 = C + (size_t)r0 * N;
        float* c1 = C + (size_t)r1 * N;
        #pragma unroll
        for (int nt = 0; nt < 4; nt++) {
            int col = n0 + wn * 32 + nt * 8 + tg * 2;
            float b0 = 0.f, b1 = 0.f;
            if (MODE == 1) { b0 = bias[col]; b1 = bias[col + 1]; }
            float2 v0 = make_float2(acc[mt][nt][0] + b0, acc[mt][nt][1] + b1);
            float2 v1 = make_float2(acc[mt][nt][2] + b0, acc[mt][nt][3] + b1);
            *(float2*)(c0 + col) = v0;
            *(float2*)(c1 + col) = v1;
        }
    }
    #undef LOAD_CHUNK
}

// ---------------- attention: 4 heads/block, 2 query rows per thread --------
// Warp = one head; lanes own rows (lane, lane+32). Every broadcast K/V smem
// read feeds TWO dot products -> LDS wavefront count halves vs round 16.
#define JCH 4
__global__ __launch_bounds__(128, 3) void attn_k()
{
    extern __shared__ float sKV[];                 // K[4][64][32] then V[4][64][32]
    float* Ks = sKV;
    float* Vs = sKV + 4 * 64 * HD;

    const int hq   = blockIdx.x;     // 0..2 head quad
    const int win  = blockIdx.y;     // 0..1023
    const int tid  = threadIdx.x;    // 0..127
    const int hl   = tid >> 5;       // 0..3 (constant per warp)
    const int lane = tid & 31;
    const int h    = hq * 4 + hl;

    const float* base = g_qkv + (size_t)win * 64 * QKVN;

    // cooperative K/V load for 4 heads: 4*64*8 float4 pairs / 128 threads
    for (int j = tid; j < 4 * 64 * 8; j += 128) {
        int hh = j >> 9;             // 0..3
        int r  = (j >> 3) & 63;
        int c  = (j & 7) * 4;
        const float* rp = base + (size_t)r * QKVN;
        int koff = CC + (hq * 4 + hh) * HD;
        int voff = 2 * CC + (hq * 4 + hh) * HD;
        *(float4*)&Ks[((hh << 6) + r) * HD + c] = *(const float4*)(rp + koff + c);
        *(float4*)&Vs[((hh << 6) + r) * HD + c] = *(const float4*)(rp + voff + c);
    }
    __syncthreads();

    const float scale = 0.17677669529663687f;  // 1/sqrt(32)
    float q0[HD], q1[HD];
    {
        const float* qp0 = base + (size_t)lane * QKVN + h * HD;
        const float* qp1 = base + (size_t)(lane + 32) * QKVN + h * HD;
        #pragma unroll
        for (int d = 0; d < HD; d += 4) {
            float4 t0 = *(const float4*)(qp0 + d);
            float4 t1 = *(const float4*)(qp1 + d);
            q0[d] = t0.x * scale; q0[d+1] = t0.y * scale; q0[d+2] = t0.z * scale; q0[d+3] = t0.w * scale;
            q1[d] = t1.x * scale; q1[d+1] = t1.y * scale; q1[d+2] = t1.z * scale; q1[d+3] = t1.w * scale;
        }
    }

    const float4* Kh = (const float4*)(Ks + ((size_t)hl << 6) * HD);  // [64][8]
    const float4* Vh = (const float4*)(Vs + ((size_t)hl << 6) * HD);

    float o0[HD] = {}, o1[HD] = {};
    float m0 = -1e30f, m1 = -1e30f, s0 = 0.f, s1 = 0.f;

    #pragma unroll 1
    for (int jc = 0; jc < 64; jc += JCH) {
        float p0[JCH], p1[JCH];
        float cm0 = -1e30f, cm1 = -1e30f;
        #pragma unroll
        for (int jj = 0; jj < JCH; jj++) {
            float a0 = 0.f, a1 = 0.f;
            #pragma unroll
            for (int d4 = 0; d4 < 8; d4++) {
                float4 kk = Kh[(jc + jj) * 8 + d4];   // broadcast, reused 2x
                int d = d4 * 4;
                a0 += q0[d] * kk.x; a1 += q1[d] * kk.x;
                a0 += q0[d+1] * kk.y; a1 += q1[d+1] * kk.y;
                a0 += q0[d+2] * kk.z; a1 += q1[d+2] * kk.z;
                a0 += q0[d+3] * kk.w; a1 += q1[d+3] * kk.w;
            }
            p0[jj] = a0; cm0 = fmaxf(cm0, a0);
            p1[jj] = a1; cm1 = fmaxf(cm1, a1);
        }
        float mn0 = fmaxf(m0, cm0), mn1 = fmaxf(m1, cm1);
        float c0 = __expf(m0 - mn0), c1 = __expf(m1 - mn1);
        s0 *= c0; s1 *= c1;
        #pragma unroll
        for (int d = 0; d < HD; d++) { o0[d] *= c0; o1[d] *= c1; }
        #pragma unroll
        for (int jj = 0; jj < JCH; jj++) {
            float e0 = __expf(p0[jj] - mn0);
            float e1 = __expf(p1[jj] - mn1);
            s0 += e0; s1 += e1;
            #pragma unroll
            for (int d4 = 0; d4 < 8; d4++) {
                float4 vv = Vh[(jc + jj) * 8 + d4];   // broadcast, reused 2x
                int d = d4 * 4;
                o0[d] += e0 * vv.x; o1[d] += e1 * vv.x;
                o0[d+1] += e0 * vv.y; o1[d+1] += e1 * vv.y;
                o0[d+2] += e0 * vv.z; o1[d+2] += e1 * vv.z;
                o0[d+3] += e0 * vv.w; o1[d+3] += e1 * vv.w;
            }
        }
        m0 = mn0; m1 = mn1;
    }

    const float i0 = 1.f / s0, i1 = 1.f / s1;
    #pragma unroll
    for (int d = 0; d < HD; d++) { o0[d] *= i0; o1[d] *= i1; }

    // write split bf16 (feeds proj GEMM): HD=32 bf16 = 4 uint4 per buffer
    __align__(16) bf16 hb[HD], lb[HD];
    #pragma unroll
    for (int d = 0; d < HD; d++) {
        bf16 hv = __float2bfloat16(o0[d]);
        hb[d] = hv;
        lb[d] = __float2bfloat16(o0[d] - __bfloat162float(hv));
    }
    size_t ob0 = (size_t)(win * 64 + lane) * CC + h * HD;
    #pragma unroll
    for (int d = 0; d < 4; d++) {
        ((uint4*)(g_ahi + ob0))[d] = ((uint4*)hb)[d];
        ((uint4*)(g_alo + ob0))[d] = ((uint4*)lb)[d];
    }
    #pragma unroll
    for (int d = 0; d < HD; d++) {
        bf16 hv = __float2bfloat16(o1[d]);
        hb[d] = hv;
        lb[d] = __float2bfloat16(o1[d] - __bfloat162float(hv));
    }
    size_t ob1 = (size_t)(win * 64 + lane + 32) * CC + h * HD;
    #pragma unroll
    for (int d = 0; d < 4; d++) {
        ((uint4*)(g_ahi + ob1))[d] = ((uint4*)hb)[d];
        ((uint4*)(g_alo + ob1))[d] = ((uint4*)lb)[d];
    }
}

// ---------------------------------------------------------------------------
extern "C" void kernel_launch(void* const* d_in, const int* in_sizes, int n_in,
                              void* d_out, int out_size)
{
    const float* x      = (const float*)d_in[0];
    const float* qkv_w  = (const float*)d_in[1];
    const float* proj_w = (const float*)d_in[2];
    const float* proj_b = (const float*)d_in[3];
    float* out = (float*)d_out;

    // device-symbol scratch address must come from the runtime (round-12 bug).
    void* qkv_p = nullptr;
    cudaGetSymbolAddress(&qkv_p, g_qkv);

    cudaFuncSetAttribute(gemm_mma<0, QKVN>, cudaFuncAttributeMaxDynamicSharedMemorySize, SM_TOTAL);
    cudaFuncSetAttribute(gemm_mma<1, CC>,   cudaFuncAttributeMaxDynamicSharedMemorySize, SM_TOTAL);
    cudaFuncSetAttribute(attn_k,            cudaFuncAttributeMaxDynamicSharedMemorySize, AT_SMEM);

    // 1) weight transpose + split (small)
    prep_w<<<(QKVN * CC + CC * CC + 255) / 256, 256>>>(qkv_w, proj_w);

    // 2) window-gather + split x
    prep_x<<<(MTOT * (CC / 4)) / 256, 256>>>(x);

    // 3) QKV projection (mma.sync tensor cores)
    gemm_mma<0, QKVN><<<dim3(QKVN / 128, MTOT / 128), 256, SM_TOTAL>>>((float*)qkv_p, nullptr);

    // 4) attention (4 heads/block, 2 query rows/thread)
    attn_k<<<dim3(NH / 4, NWIN), 128, AT_SMEM>>>();

    // 5) output projection + bias + scatter (mma.sync tensor cores)
    gemm_mma<1, CC><<<dim3(CC / 128, MTOT / 128), 256, SM_TOTAL>>>(out, proj_b);
}